// round 9
// baseline (speedup 1.0000x reference)
#include <cuda_runtime.h>
#include <cuda_fp16.h>
#include <cstdint>

// Problem constants
#define BB   2048
#define DD   256
#define OUTN 256
#define KK   16
#define DKN  (DD * KK)   // 4096 = GEMM K

// GEMM tiling
#define MT      64                 // CTA M tile
#define NT      64                 // CTA N tile
#define KC      64                 // halfs per K chunk (=128B rows)
#define NKCH    (DKN / KC)         // 64 chunks
#define STAGES  3
#define ASTG    8192               // A: 64 rows x 128B (built in-place from x)
#define BSTG    8192               // B: 64 rows x 128B (cp.async)
#define STG_BYTES (ASTG + BSTG)
#define SMEM_BYTES (STAGES * STG_BYTES)   // 48KB

// Scratch (device global; no allocation allowed)
__device__ __half g_V[OUTN * DKN];   // [o][dk] fp16, 2 MB

__constant__ float c_grid[16] = {
    -1.0f,         -0.86666667f, -0.73333333f, -0.6f,
    -0.46666667f,  -0.33333334f, -0.2f,        -0.06666667f,
     0.06666667f,   0.2f,         0.33333333f,  0.46666667f,
     0.6f,          0.73333333f,  0.86666667f,  1.0f
};

// ---------------------------------------------------------------------------
// Bucketize (validated semantics R1-R8)
// ---------------------------------------------------------------------------
__device__ __forceinline__ void bucketize(float xv, int& l, float& w) {
    float xc = fminf(fmaxf(xv, -1.0f), 1.0f);
    float t = (xc + 1.0f) * 7.5f;
    int j = (int)t;
    if (j > 14) j = 14;
    if (j > 0 && xc <= c_grid[j]) {
        --j;
    } else if (j < 14 && xc > c_grid[j + 1]) {
        ++j;
    }
    float ww = (xc - c_grid[j]) / (c_grid[j + 1] - c_grid[j]);
    w = fminf(fmaxf(ww, 0.0f), 1.0f);
    l = j;
}

// ---------------------------------------------------------------------------
// Kernel 1: V'[o][dk] = half(values[o][dk] + grid[dk&15]*skip_w[o][dk>>4])
// 8 halfs per thread (8-aligned blocks never cross a d group of 16).
// ---------------------------------------------------------------------------
__global__ void k_build_v(const float* __restrict__ vals,
                          const float* __restrict__ sw) {
    int id8  = blockIdx.x * 256 + threadIdx.x;   // 0 .. 131071
    int base = id8 * 8;
    int o  = base >> 12;
    int dk = base & 4095;
    float swv = sw[o * DD + (dk >> 4)];
    float4 v0 = *(const float4*)(vals + base);
    float4 v1 = *(const float4*)(vals + base + 4);
    const float* gr = c_grid + (dk & 15);

    __half hv[8];
    hv[0] = __float2half_rn(v0.x + gr[0] * swv);
    hv[1] = __float2half_rn(v0.y + gr[1] * swv);
    hv[2] = __float2half_rn(v0.z + gr[2] * swv);
    hv[3] = __float2half_rn(v0.w + gr[3] * swv);
    hv[4] = __float2half_rn(v1.x + gr[4] * swv);
    hv[5] = __float2half_rn(v1.y + gr[5] * swv);
    hv[6] = __float2half_rn(v1.z + gr[6] * swv);
    hv[7] = __float2half_rn(v1.w + gr[7] * swv);
    *(uint4*)(g_V + base) = *(const uint4*)hv;
}

// ---------------------------------------------------------------------------
// On-the-fly Phi tile generation (fp16, identical rounding to R8's k_build_phi)
// ---------------------------------------------------------------------------
__device__ __forceinline__ void phi_pair(float xv, uint32_t* h /*[8] half2*/) {
    int l; float w;
    bucketize(xv, l, w);
    float f0 = 1.0f - w;
    uint32_t wv;   // {lo = f0, hi = w}
    asm("cvt.rn.f16x2.f32 %0, %1, %2;" : "=r"(wv) : "f"(w), "f"(f0));
    int  odd = l & 1;
    uint32_t A = odd ? (wv << 16) : wv;    // odd: pack(0, f0)
    uint32_t B = odd ? (wv >> 16) : 0u;    // odd: pack(w, 0)
    int pA = l >> 1;
    int pB = odd ? (pA + 1) : 8;           // 8 = never matches
#pragma unroll
    for (int i = 0; i < 8; ++i)
        h[i] = (i == pA) ? A : ((i == pB) ? B : 0u);
}

__device__ __forceinline__ void phi_store(uint32_t sbase, int b, int dl,
                                          const uint32_t* h) {
    int cb0 = dl * 2;
    uint32_t a0 = sbase + b * 128 + (((cb0)     ^ (b & 7)) << 4);
    uint32_t a1 = sbase + b * 128 + (((cb0 + 1) ^ (b & 7)) << 4);
    asm volatile("st.shared.v4.b32 [%0], {%1,%2,%3,%4};"
                 :: "r"(a0), "r"(h[0]), "r"(h[1]), "r"(h[2]), "r"(h[3]) : "memory");
    asm volatile("st.shared.v4.b32 [%0], {%1,%2,%3,%4};"
                 :: "r"(a1), "r"(h[4]), "r"(h[5]), "r"(h[6]), "r"(h[7]) : "memory");
}

// Thread tid builds (b = tid&63, d pair dp = tid>>6) of the 64x64 Phi tile.
__device__ __forceinline__ void build_phi_stage(uint32_t sb, int slot,
                                                float2 xv, int tid) {
    int b  = tid & 63;
    int dp = tid >> 6;
    uint32_t sbase = sb + slot * STG_BYTES;
    uint32_t h[8];
    phi_pair(xv.x, h);
    phi_store(sbase, b, dp * 2, h);
    phi_pair(xv.y, h);
    phi_store(sbase, b, dp * 2 + 1, h);
}

// B-tile staging via cp.async (swizzled, 4x16B per thread)
__device__ __forceinline__ void load_b_stage(uint32_t sb, const char* gB,
                                             int kt, int slot, int tid) {
    uint32_t dstB = sb + slot * STG_BYTES + ASTG;
    const char* srcB = gB + kt * 128;
#pragma unroll
    for (int i = 0; i < 4; ++i) {
        int idx = i * 128 + tid;
        int row = idx >> 3;
        int cb  = idx & 7;
        uint32_t swz = row * 128 + ((cb ^ (row & 7)) << 4);
        asm volatile("cp.async.cg.shared.global [%0], [%1], 16;"
                     :: "r"(dstB + swz), "l"(srcB + row * 8192 + cb * 16)
                     : "memory");
    }
}

// ---------------------------------------------------------------------------
// Kernel 2: HMMA GEMM  y[2048,256] = Phi(x) @ V'^T + bias, Phi on the fly.
// CTA 64x64, 4 warps (2x2, warp tile 32x32), 3-stage pipeline.
// ---------------------------------------------------------------------------
#define LDMX4(r0, r1, r2, r3, addr)                                       \
    asm volatile("ldmatrix.sync.aligned.m8n8.x4.shared.b16 "              \
                 "{%0,%1,%2,%3}, [%4];"                                   \
                 : "=r"(r0), "=r"(r1), "=r"(r2), "=r"(r3) : "r"(addr))

#define MMA16816(c, a0, a1, a2, a3, b0, b1)                               \
    asm volatile("mma.sync.aligned.m16n8k16.row.col.f32.f16.f16.f32 "     \
                 "{%0,%1,%2,%3}, {%4,%5,%6,%7}, {%8,%9}, {%0,%1,%2,%3};"  \
                 : "+f"(c[0]), "+f"(c[1]), "+f"(c[2]), "+f"(c[3])         \
                 : "r"(a0), "r"(a1), "r"(a2), "r"(a3), "r"(b0), "r"(b1))

__global__ __launch_bounds__(128) void k_gemm(const float* __restrict__ x,
                                              const float* __restrict__ skip_b,
                                              float* __restrict__ y) {
    extern __shared__ char smem[];
    uint32_t sb;
    asm("{ .reg .u64 t; cvta.to.shared.u64 t, %1; cvt.u32.u64 %0, t; }"
        : "=r"(sb) : "l"(smem));

    const int tid  = threadIdx.x;
    const int wid  = tid >> 5;
    const int lane = tid & 31;
    const int wm   = (wid & 1) * 32;
    const int wn   = (wid >> 1) * 32;
    const int mt   = blockIdx.x >> 2;
    const int nt   = blockIdx.x & 3;
    const int b0   = mt * MT;
    const char* gB = (const char*)g_V + (size_t)nt * NT * 8192;

    // x prefetch address for this thread: row b0+(tid&63), d = 4*kt + 2*(tid>>6)
    const float* xp = x + (b0 + (tid & 63)) * DD + (tid >> 6) * 2;

    const int lrow = lane & 15;
    const int lcb  = lane >> 4;

    // Prologue: stage chunks 0 and 1
    {
        float2 xv0 = *(const float2*)(xp + 0 * 4);
        float2 xv1 = *(const float2*)(xp + 1 * 4);
        load_b_stage(sb, gB, 0, 0, tid);
        asm volatile("cp.async.commit_group;" ::: "memory");
        load_b_stage(sb, gB, 1, 1, tid);
        asm volatile("cp.async.commit_group;" ::: "memory");
        build_phi_stage(sb, 0, xv0, tid);
        build_phi_stage(sb, 1, xv1, tid);
    }

    float acc[2][4][4];
#pragma unroll
    for (int mi = 0; mi < 2; ++mi)
#pragma unroll
        for (int ni = 0; ni < 4; ++ni)
#pragma unroll
            for (int j = 0; j < 4; ++j) acc[mi][ni][j] = 0.f;

    const int arow0 = wm + lrow, arow1 = wm + 16 + lrow;
    const int brow0 = wn + lrow, brow1 = wn + 16 + lrow;

#pragma unroll 1
    for (int kt = 0; kt < NKCH; ++kt) {
        asm volatile("cp.async.wait_group 1;" ::: "memory");
        __syncthreads();

        float2 xv = make_float2(0.f, 0.f);
        const bool pf = (kt + 2 < NKCH);
        if (pf) {
            xv = *(const float2*)(xp + (kt + 2) * 4);   // LDG early
            load_b_stage(sb, gB, kt + 2, (kt + 2) % STAGES, tid);
        }
        asm volatile("cp.async.commit_group;" ::: "memory");

        uint32_t sA = sb + (kt % STAGES) * STG_BYTES;
        uint32_t sB = sA + ASTG;

#pragma unroll
        for (int k16 = 0; k16 < 4; ++k16) {
            int cu = k16 * 2 + lcb;
            uint32_t a0, a1, a2, a3, a4, a5, a6, a7;
            uint32_t b0r, b1r, b2r, b3r, b4r, b5r, b6r, b7r;
            LDMX4(a0, a1, a2, a3, sA + arow0 * 128 + ((cu ^ (arow0 & 7)) << 4));
            LDMX4(a4, a5, a6, a7, sA + arow1 * 128 + ((cu ^ (arow1 & 7)) << 4));
            LDMX4(b0r, b1r, b2r, b3r, sB + brow0 * 128 + ((cu ^ (brow0 & 7)) << 4));
            LDMX4(b4r, b5r, b6r, b7r, sB + brow1 * 128 + ((cu ^ (brow1 & 7)) << 4));

            MMA16816(acc[0][0], a0, a1, a2, a3, b0r, b2r);
            MMA16816(acc[0][1], a0, a1, a2, a3, b1r, b3r);
            MMA16816(acc[0][2], a0, a1, a2, a3, b4r, b6r);
            MMA16816(acc[0][3], a0, a1, a2, a3, b5r, b7r);
            MMA16816(acc[1][0], a4, a5, a6, a7, b0r, b2r);
            MMA16816(acc[1][1], a4, a5, a6, a7, b1r, b3r);
            MMA16816(acc[1][2], a4, a5, a6, a7, b4r, b6r);
            MMA16816(acc[1][3], a4, a5, a6, a7, b5r, b7r);
        }

        // Build Phi for chunk kt+2 AFTER compute (LDG latency already covered)
        if (pf)
            build_phi_stage(sb, (kt + 2) % STAGES, xv, tid);
    }

    // Epilogue: add bias, store
    const int m0 = mt * MT + wm + (lane >> 2);
    const int nb = nt * NT + wn + (lane & 3) * 2;
#pragma unroll
    for (int mi = 0; mi < 2; ++mi) {
#pragma unroll
        for (int ni = 0; ni < 4; ++ni) {
            int n = nb + ni * 8;
            float2 bias = *(const float2*)(skip_b + n);
            int m = m0 + mi * 16;
            float2 r0 = make_float2(acc[mi][ni][0] + bias.x,
                                    acc[mi][ni][1] + bias.y);
            float2 r1 = make_float2(acc[mi][ni][2] + bias.x,
                                    acc[mi][ni][3] + bias.y);
            *(float2*)(y + m * OUTN + n)       = r0;
            *(float2*)(y + (m + 8) * OUTN + n) = r1;
        }
    }
}

// ---------------------------------------------------------------------------
extern "C" void kernel_launch(void* const* d_in, const int* in_sizes, int n_in,
                              void* d_out, int out_size) {
    const float* x      = (const float*)d_in[0];  // (B, D)
    const float* values = (const float*)d_in[1];  // (OUT, D, K)
    const float* skip_w = (const float*)d_in[2];  // (OUT, D)
    const float* skip_b = (const float*)d_in[3];  // (OUT,)
    float* y = (float*)d_out;                     // (B, OUT)

    cudaFuncSetAttribute(k_gemm, cudaFuncAttributeMaxDynamicSharedMemorySize,
                         SMEM_BYTES);

    k_build_v<<<(OUTN * DKN) / (256 * 8), 256>>>(values, skip_w);
    k_gemm<<<(BB / MT) * (OUTN / NT), 128, SMEM_BYTES>>>(x, skip_b, y);
}

// round 10
// speedup vs baseline: 3.3754x; 3.3754x over previous
#include <cuda_runtime.h>
#include <cuda_fp16.h>
#include <cstdint>

// Problem constants
#define BB   2048
#define DD   256
#define OUTN 256
#define KK   16
#define DKN  (DD * KK)   // 4096 = GEMM K

// GEMM tiling
#define MT      64                 // CTA M tile
#define NT      64                 // CTA N tile
#define KSPLIT  4
#define NKCH_S  16                 // chunks per K-split (64 total / 4)
#define MTILES  (BB / MT)          // 32
#define NTILES  (OUTN / NT)        // 4
#define STAGES  3
#define ASTG    8192               // 64 rows x 128B
#define BSTG    8192
#define STG_BYTES (ASTG + BSTG)
#define SMEM_BYTES (STAGES * STG_BYTES)   // 48KB

// Scratch (device globals; no allocation allowed)
__device__ __half g_Phi[BB * DKN];            // 16 MB
__device__ __half g_V[OUTN * DKN];            //  2 MB
__device__ float  g_part[KSPLIT * BB * OUTN]; //  8 MB fp32 partials

__constant__ float c_grid[16] = {
    -1.0f,         -0.86666667f, -0.73333333f, -0.6f,
    -0.46666667f,  -0.33333334f, -0.2f,        -0.06666667f,
     0.06666667f,   0.2f,         0.33333333f,  0.46666667f,
     0.6f,          0.73333333f,  0.86666667f,  1.0f
};

// ---------------------------------------------------------------------------
// Bucketize (validated semantics R1-R9)
// ---------------------------------------------------------------------------
__device__ __forceinline__ void bucketize(float xv, int& l, float& w) {
    float xc = fminf(fmaxf(xv, -1.0f), 1.0f);
    float t = (xc + 1.0f) * 7.5f;
    int j = (int)t;
    if (j > 14) j = 14;
    if (j > 0 && xc <= c_grid[j]) {
        --j;
    } else if (j < 14 && xc > c_grid[j + 1]) {
        ++j;
    }
    float ww = (xc - c_grid[j]) / (c_grid[j + 1] - c_grid[j]);
    w = fminf(fmaxf(ww, 0.0f), 1.0f);
    l = j;
}

// ---------------------------------------------------------------------------
// Kernel 1: V' build, 8 halfs/thread (validated R9)
// ---------------------------------------------------------------------------
__global__ void k_build_v(const float* __restrict__ vals,
                          const float* __restrict__ sw) {
    int id8  = blockIdx.x * 256 + threadIdx.x;
    int base = id8 * 8;
    int o  = base >> 12;
    int dk = base & 4095;
    float swv = sw[o * DD + (dk >> 4)];
    float4 v0 = *(const float4*)(vals + base);
    float4 v1 = *(const float4*)(vals + base + 4);
    const float* gr = c_grid + (dk & 15);

    __half hv[8];
    hv[0] = __float2half_rn(v0.x + gr[0] * swv);
    hv[1] = __float2half_rn(v0.y + gr[1] * swv);
    hv[2] = __float2half_rn(v0.z + gr[2] * swv);
    hv[3] = __float2half_rn(v0.w + gr[3] * swv);
    hv[4] = __float2half_rn(v1.x + gr[4] * swv);
    hv[5] = __float2half_rn(v1.y + gr[5] * swv);
    hv[6] = __float2half_rn(v1.z + gr[6] * swv);
    hv[7] = __float2half_rn(v1.w + gr[7] * swv);
    *(uint4*)(g_V + base) = *(const uint4*)hv;
}

// ---------------------------------------------------------------------------
// Kernel 2: Phi build (validated R8)
// ---------------------------------------------------------------------------
__global__ void k_build_phi(const float* __restrict__ x) {
    int b = blockIdx.x;
    int d = threadIdx.x;
    int l; float w;
    bucketize(x[b * DD + d], l, w);

    __half hv[16];
#pragma unroll
    for (int i = 0; i < 16; ++i) {
        float f = (i == l) ? (1.0f - w) : ((i == l + 1) ? w : 0.0f);
        hv[i] = __float2half_rn(f);
    }
    __half* dst = g_Phi + b * DKN + d * 16;
    *(uint4*)(dst)     = *(const uint4*)&hv[0];
    *(uint4*)(dst + 8) = *(const uint4*)&hv[8];
}

// ---------------------------------------------------------------------------
// Kernel 3: HMMA GEMM with K-split=4. 512 CTAs, 128 threads.
// Each CTA: 64x64 output tile over a 1024-wide K slice -> fp32 partial.
// Core pipeline identical to validated R8.
// ---------------------------------------------------------------------------
#define LDMX4(r0, r1, r2, r3, addr)                                       \
    asm volatile("ldmatrix.sync.aligned.m8n8.x4.shared.b16 "              \
                 "{%0,%1,%2,%3}, [%4];"                                   \
                 : "=r"(r0), "=r"(r1), "=r"(r2), "=r"(r3) : "r"(addr))

#define MMA16816(c, a0, a1, a2, a3, b0, b1)                               \
    asm volatile("mma.sync.aligned.m16n8k16.row.col.f32.f16.f16.f32 "     \
                 "{%0,%1,%2,%3}, {%4,%5,%6,%7}, {%8,%9}, {%0,%1,%2,%3};"  \
                 : "+f"(c[0]), "+f"(c[1]), "+f"(c[2]), "+f"(c[3])         \
                 : "r"(a0), "r"(a1), "r"(a2), "r"(a3), "r"(b0), "r"(b1))

__device__ __forceinline__ void load_stage(uint32_t sb, const char* gA,
                                           const char* gB, int kt, int slot,
                                           int tid) {
    uint32_t dstA = sb + slot * STG_BYTES;
    uint32_t dstB = dstA + ASTG;
    const char* srcA = gA + kt * 128;
    const char* srcB = gB + kt * 128;
#pragma unroll
    for (int i = 0; i < 4; ++i) {
        int idx = i * 128 + tid;
        int row = idx >> 3;
        int cb  = idx & 7;
        uint32_t swz = row * 128 + ((cb ^ (row & 7)) << 4);
        asm volatile("cp.async.cg.shared.global [%0], [%1], 16;"
                     :: "r"(dstA + swz), "l"(srcA + row * 8192 + cb * 16)
                     : "memory");
        asm volatile("cp.async.cg.shared.global [%0], [%1], 16;"
                     :: "r"(dstB + swz), "l"(srcB + row * 8192 + cb * 16)
                     : "memory");
    }
}

__global__ __launch_bounds__(128) void k_gemm(float* __restrict__ part) {
    extern __shared__ char smem[];
    uint32_t sb;
    asm("{ .reg .u64 t; cvta.to.shared.u64 t, %1; cvt.u32.u64 %0, t; }"
        : "=r"(sb) : "l"(smem));

    const int tid  = threadIdx.x;
    const int wid  = tid >> 5;
    const int lane = tid & 31;
    const int wm   = (wid & 1) * 32;
    const int wn   = (wid >> 1) * 32;
    const int ks   = blockIdx.x >> 7;                // 0..3
    const int mt   = (blockIdx.x >> 2) & 31;         // 0..31
    const int nt   = blockIdx.x & 3;                 // 0..3
    // base pointers include the K-split column offset (16 chunks x 128B)
    const char* gA = (const char*)g_Phi + (size_t)mt * MT * 8192 + ks * NKCH_S * 128;
    const char* gB = (const char*)g_V   + (size_t)nt * NT * 8192 + ks * NKCH_S * 128;

    const int lrow = lane & 15;
    const int lcb  = lane >> 4;

    load_stage(sb, gA, gB, 0, 0, tid);
    asm volatile("cp.async.commit_group;" ::: "memory");
    load_stage(sb, gA, gB, 1, 1, tid);
    asm volatile("cp.async.commit_group;" ::: "memory");

    float acc[2][4][4];
#pragma unroll
    for (int mi = 0; mi < 2; ++mi)
#pragma unroll
        for (int ni = 0; ni < 4; ++ni)
#pragma unroll
            for (int j = 0; j < 4; ++j) acc[mi][ni][j] = 0.f;

    const int arow0 = wm + lrow, arow1 = wm + 16 + lrow;
    const int brow0 = wn + lrow, brow1 = wn + 16 + lrow;

#pragma unroll 1
    for (int kt = 0; kt < NKCH_S; ++kt) {
        asm volatile("cp.async.wait_group 1;" ::: "memory");
        __syncthreads();

        if (kt + 2 < NKCH_S)
            load_stage(sb, gA, gB, kt + 2, (kt + 2) % STAGES, tid);
        asm volatile("cp.async.commit_group;" ::: "memory");

        uint32_t sA = sb + (kt % STAGES) * STG_BYTES;
        uint32_t sB = sA + ASTG;

#pragma unroll
        for (int k16 = 0; k16 < 4; ++k16) {
            int cu = k16 * 2 + lcb;
            uint32_t a0, a1, a2, a3, a4, a5, a6, a7;
            uint32_t b0, b1, b2, b3, b4, b5, b6, b7;
            LDMX4(a0, a1, a2, a3, sA + arow0 * 128 + ((cu ^ (arow0 & 7)) << 4));
            LDMX4(a4, a5, a6, a7, sA + arow1 * 128 + ((cu ^ (arow1 & 7)) << 4));
            LDMX4(b0, b1, b2, b3, sB + brow0 * 128 + ((cu ^ (brow0 & 7)) << 4));
            LDMX4(b4, b5, b6, b7, sB + brow1 * 128 + ((cu ^ (brow1 & 7)) << 4));

            MMA16816(acc[0][0], a0, a1, a2, a3, b0, b2);
            MMA16816(acc[0][1], a0, a1, a2, a3, b1, b3);
            MMA16816(acc[0][2], a0, a1, a2, a3, b4, b6);
            MMA16816(acc[0][3], a0, a1, a2, a3, b5, b7);
            MMA16816(acc[1][0], a4, a5, a6, a7, b0, b2);
            MMA16816(acc[1][1], a4, a5, a6, a7, b1, b3);
            MMA16816(acc[1][2], a4, a5, a6, a7, b4, b6);
            MMA16816(acc[1][3], a4, a5, a6, a7, b5, b7);
        }
    }

    // Epilogue: store fp32 partial (no bias here)
    float* pout = part + (size_t)ks * (BB * OUTN);
    const int m0 = mt * MT + wm + (lane >> 2);
    const int nb = nt * NT + wn + (lane & 3) * 2;
#pragma unroll
    for (int mi = 0; mi < 2; ++mi) {
#pragma unroll
        for (int ni = 0; ni < 4; ++ni) {
            int n = nb + ni * 8;
            int m = m0 + mi * 16;
            *(float2*)(pout + m * OUTN + n) =
                make_float2(acc[mi][ni][0], acc[mi][ni][1]);
            *(float2*)(pout + (m + 8) * OUTN + n) =
                make_float2(acc[mi][ni][2], acc[mi][ni][3]);
        }
    }
}

// ---------------------------------------------------------------------------
// Kernel 4: reduce partials + bias. float4 per thread.
// ---------------------------------------------------------------------------
__global__ void k_reduce(const float* __restrict__ skip_b,
                         float* __restrict__ y) {
    int id = blockIdx.x * 256 + threadIdx.x;   // 0 .. 131071
    int base = id * 4;
    int n = base & (OUTN - 1);
    float4 s = *(const float4*)(skip_b + n);
#pragma unroll
    for (int ks = 0; ks < KSPLIT; ++ks) {
        float4 p = *(const float4*)(g_part + (size_t)ks * (BB * OUTN) + base);
        s.x += p.x; s.y += p.y; s.z += p.z; s.w += p.w;
    }
    *(float4*)(y + base) = s;
}

// ---------------------------------------------------------------------------
extern "C" void kernel_launch(void* const* d_in, const int* in_sizes, int n_in,
                              void* d_out, int out_size) {
    const float* x      = (const float*)d_in[0];  // (B, D)
    const float* values = (const float*)d_in[1];  // (OUT, D, K)
    const float* skip_w = (const float*)d_in[2];  // (OUT, D)
    const float* skip_b = (const float*)d_in[3];  // (OUT,)
    float* y = (float*)d_out;                     // (B, OUT)

    cudaFuncSetAttribute(k_gemm, cudaFuncAttributeMaxDynamicSharedMemorySize,
                         SMEM_BYTES);

    float* part;
    cudaGetSymbolAddress((void**)&part, g_part);

    k_build_v<<<(OUTN * DKN) / (256 * 8), 256>>>(values, skip_w);
    k_build_phi<<<BB, DD>>>(x);
    k_gemm<<<KSPLIT * MTILES * NTILES, 128, SMEM_BYTES>>>(part);
    k_reduce<<<(BB * OUTN) / (256 * 4), 256>>>(skip_b, y);
}

// round 11
// speedup vs baseline: 3.5951x; 1.0651x over previous
#include <cuda_runtime.h>
#include <cuda_fp16.h>
#include <cstdint>

// Problem constants
#define BB   2048
#define DD   256
#define OUTN 256
#define KK   16
#define DKN  (DD * KK)   // 4096 = GEMM K

// GEMM tiling
#define MT      128                // CTA M tile
#define NT      64                 // CTA N tile
#define KSPLIT  4
#define NKCH_S  16                 // chunks per K-split (64 total / 4)
#define MTILES  (BB / MT)          // 16
#define NTILES  (OUTN / NT)        // 4
#define STAGES  3
#define ASTG    16384              // 128 rows x 128B
#define BSTG    8192               // 64 rows x 128B
#define STG_BYTES (ASTG + BSTG)    // 24KB
#define SMEM_BYTES (STAGES * STG_BYTES)   // 72KB

// Scratch (device globals; no allocation allowed)
__device__ __half g_Phi[BB * DKN];            // 16 MB
__device__ __half g_V[OUTN * DKN];            //  2 MB
__device__ float  g_part[KSPLIT * BB * OUTN]; //  8 MB fp32 partials

__constant__ float c_grid[16] = {
    -1.0f,         -0.86666667f, -0.73333333f, -0.6f,
    -0.46666667f,  -0.33333334f, -0.2f,        -0.06666667f,
     0.06666667f,   0.2f,         0.33333333f,  0.46666667f,
     0.6f,          0.73333333f,  0.86666667f,  1.0f
};

// ---------------------------------------------------------------------------
// Bucketize (validated semantics R1-R10)
// ---------------------------------------------------------------------------
__device__ __forceinline__ void bucketize(float xv, int& l, float& w) {
    float xc = fminf(fmaxf(xv, -1.0f), 1.0f);
    float t = (xc + 1.0f) * 7.5f;
    int j = (int)t;
    if (j > 14) j = 14;
    if (j > 0 && xc <= c_grid[j]) {
        --j;
    } else if (j < 14 && xc > c_grid[j + 1]) {
        ++j;
    }
    float ww = (xc - c_grid[j]) / (c_grid[j + 1] - c_grid[j]);
    w = fminf(fmaxf(ww, 0.0f), 1.0f);
    l = j;
}

// ---------------------------------------------------------------------------
// Kernel 1: merged build. Blocks [0, 512) build V' (8 halfs/thread, validated
// R9/R10); blocks [512, 2560) build Phi rows (validated R8/R10).
// ---------------------------------------------------------------------------
#define VBLKS 512
__global__ void k_build(const float* __restrict__ vals,
                        const float* __restrict__ sw,
                        const float* __restrict__ x) {
    int bid = blockIdx.x;
    int tid = threadIdx.x;
    if (bid < VBLKS) {
        int base = (bid * 256 + tid) * 8;
        int o  = base >> 12;
        int dk = base & 4095;
        float swv = sw[o * DD + (dk >> 4)];
        float4 v0 = *(const float4*)(vals + base);
        float4 v1 = *(const float4*)(vals + base + 4);
        const float* gr = c_grid + (dk & 15);

        __half hv[8];
        hv[0] = __float2half_rn(v0.x + gr[0] * swv);
        hv[1] = __float2half_rn(v0.y + gr[1] * swv);
        hv[2] = __float2half_rn(v0.z + gr[2] * swv);
        hv[3] = __float2half_rn(v0.w + gr[3] * swv);
        hv[4] = __float2half_rn(v1.x + gr[4] * swv);
        hv[5] = __float2half_rn(v1.y + gr[5] * swv);
        hv[6] = __float2half_rn(v1.z + gr[6] * swv);
        hv[7] = __float2half_rn(v1.w + gr[7] * swv);
        *(uint4*)(g_V + base) = *(const uint4*)hv;
    } else {
        int b = bid - VBLKS;
        int d = tid;
        int l; float w;
        bucketize(x[b * DD + d], l, w);

        __half hv[16];
#pragma unroll
        for (int i = 0; i < 16; ++i) {
            float f = (i == l) ? (1.0f - w) : ((i == l + 1) ? w : 0.0f);
            hv[i] = __float2half_rn(f);
        }
        __half* dst = g_Phi + b * DKN + d * 16;
        *(uint4*)(dst)     = *(const uint4*)&hv[0];
        *(uint4*)(dst + 8) = *(const uint4*)&hv[8];
    }
}

// ---------------------------------------------------------------------------
// Kernel 2: HMMA GEMM, K-split=4. 256 CTAs x 256 threads (8 warps, 4x2 of
// 32x32 warp tiles). Each CTA: 128x64 output over a 1024-wide K slice.
// Pipeline and warp-level fragment code identical to validated R10.
// ---------------------------------------------------------------------------
#define LDMX4(r0, r1, r2, r3, addr)                                       \
    asm volatile("ldmatrix.sync.aligned.m8n8.x4.shared.b16 "              \
                 "{%0,%1,%2,%3}, [%4];"                                   \
                 : "=r"(r0), "=r"(r1), "=r"(r2), "=r"(r3) : "r"(addr))

#define MMA16816(c, a0, a1, a2, a3, b0, b1)                               \
    asm volatile("mma.sync.aligned.m16n8k16.row.col.f32.f16.f16.f32 "     \
                 "{%0,%1,%2,%3}, {%4,%5,%6,%7}, {%8,%9}, {%0,%1,%2,%3};"  \
                 : "+f"(c[0]), "+f"(c[1]), "+f"(c[2]), "+f"(c[3])         \
                 : "r"(a0), "r"(a1), "r"(a2), "r"(a3), "r"(b0), "r"(b1))

__device__ __forceinline__ void load_stage(uint32_t sb, const char* gA,
                                           const char* gB, int kt, int slot,
                                           int tid) {
    uint32_t dstA = sb + slot * STG_BYTES;
    uint32_t dstB = dstA + ASTG;
    const char* srcA = gA + kt * 128;
    const char* srcB = gB + kt * 128;
    // A: 128 rows x 8 16B-units = 1024 units; 256 threads -> 4 each
#pragma unroll
    for (int i = 0; i < 4; ++i) {
        int idx = i * 256 + tid;
        int row = idx >> 3;
        int cb  = idx & 7;
        uint32_t swz = row * 128 + ((cb ^ (row & 7)) << 4);
        asm volatile("cp.async.cg.shared.global [%0], [%1], 16;"
                     :: "r"(dstA + swz), "l"(srcA + row * 8192 + cb * 16)
                     : "memory");
    }
    // B: 64 rows x 8 units = 512 units; 2 each
#pragma unroll
    for (int i = 0; i < 2; ++i) {
        int idx = i * 256 + tid;
        int row = idx >> 3;
        int cb  = idx & 7;
        uint32_t swz = row * 128 + ((cb ^ (row & 7)) << 4);
        asm volatile("cp.async.cg.shared.global [%0], [%1], 16;"
                     :: "r"(dstB + swz), "l"(srcB + row * 8192 + cb * 16)
                     : "memory");
    }
}

__global__ __launch_bounds__(256) void k_gemm(float* __restrict__ part) {
    extern __shared__ char smem[];
    uint32_t sb;
    asm("{ .reg .u64 t; cvta.to.shared.u64 t, %1; cvt.u32.u64 %0, t; }"
        : "=r"(sb) : "l"(smem));

    const int tid  = threadIdx.x;
    const int wid  = tid >> 5;
    const int lane = tid & 31;
    const int wm   = (wid & 3) * 32;                 // 4 warps down M
    const int wn   = (wid >> 2) * 32;                // 2 warps across N
    const int ks   = blockIdx.x >> 6;                // 0..3
    const int mt   = (blockIdx.x >> 2) & 15;         // 0..15
    const int nt   = blockIdx.x & 3;                 // 0..3
    const char* gA = (const char*)g_Phi + (size_t)mt * MT * 8192 + ks * NKCH_S * 128;
    const char* gB = (const char*)g_V   + (size_t)nt * NT * 8192 + ks * NKCH_S * 128;

    const int lrow = lane & 15;
    const int lcb  = lane >> 4;

    load_stage(sb, gA, gB, 0, 0, tid);
    asm volatile("cp.async.commit_group;" ::: "memory");
    load_stage(sb, gA, gB, 1, 1, tid);
    asm volatile("cp.async.commit_group;" ::: "memory");

    float acc[2][4][4];
#pragma unroll
    for (int mi = 0; mi < 2; ++mi)
#pragma unroll
        for (int ni = 0; ni < 4; ++ni)
#pragma unroll
            for (int j = 0; j < 4; ++j) acc[mi][ni][j] = 0.f;

    const int arow0 = wm + lrow, arow1 = wm + 16 + lrow;
    const int brow0 = wn + lrow, brow1 = wn + 16 + lrow;

#pragma unroll 1
    for (int kt = 0; kt < NKCH_S; ++kt) {
        asm volatile("cp.async.wait_group 1;" ::: "memory");
        __syncthreads();

        if (kt + 2 < NKCH_S)
            load_stage(sb, gA, gB, kt + 2, (kt + 2) % STAGES, tid);
        asm volatile("cp.async.commit_group;" ::: "memory");

        uint32_t sA = sb + (kt % STAGES) * STG_BYTES;
        uint32_t sB = sA + ASTG;

#pragma unroll
        for (int k16 = 0; k16 < 4; ++k16) {
            int cu = k16 * 2 + lcb;
            uint32_t a0, a1, a2, a3, a4, a5, a6, a7;
            uint32_t b0, b1, b2, b3, b4, b5, b6, b7;
            LDMX4(a0, a1, a2, a3, sA + arow0 * 128 + ((cu ^ (arow0 & 7)) << 4));
            LDMX4(a4, a5, a6, a7, sA + arow1 * 128 + ((cu ^ (arow1 & 7)) << 4));
            LDMX4(b0, b1, b2, b3, sB + brow0 * 128 + ((cu ^ (brow0 & 7)) << 4));
            LDMX4(b4, b5, b6, b7, sB + brow1 * 128 + ((cu ^ (brow1 & 7)) << 4));

            MMA16816(acc[0][0], a0, a1, a2, a3, b0, b2);
            MMA16816(acc[0][1], a0, a1, a2, a3, b1, b3);
            MMA16816(acc[0][2], a0, a1, a2, a3, b4, b6);
            MMA16816(acc[0][3], a0, a1, a2, a3, b5, b7);
            MMA16816(acc[1][0], a4, a5, a6, a7, b0, b2);
            MMA16816(acc[1][1], a4, a5, a6, a7, b1, b3);
            MMA16816(acc[1][2], a4, a5, a6, a7, b4, b6);
            MMA16816(acc[1][3], a4, a5, a6, a7, b5, b7);
        }
    }

    // Epilogue: store fp32 partial
    float* pout = part + (size_t)ks * (BB * OUTN);
    const int m0 = mt * MT + wm + (lane >> 2);
    const int nb = nt * NT + wn + (lane & 3) * 2;
#pragma unroll
    for (int mi = 0; mi < 2; ++mi) {
#pragma unroll
        for (int ni = 0; ni < 4; ++ni) {
            int n = nb + ni * 8;
            int m = m0 + mi * 16;
            *(float2*)(pout + m * OUTN + n) =
                make_float2(acc[mi][ni][0], acc[mi][ni][1]);
            *(float2*)(pout + (m + 8) * OUTN + n) =
                make_float2(acc[mi][ni][2], acc[mi][ni][3]);
        }
    }
}

// ---------------------------------------------------------------------------
// Kernel 3: reduce partials + bias. 2 float4 per thread, 8 independent loads.
// ---------------------------------------------------------------------------
#define RHALF (BB * OUTN / 8)   // 65536 float4s per half
__global__ void k_reduce(const float* __restrict__ skip_b,
                         float* __restrict__ y) {
    int gid = blockIdx.x * 256 + threadIdx.x;   // 0 .. 65535
#pragma unroll
    for (int j = 0; j < 2; ++j) {
        int base = (gid + j * RHALF) * 4;
        int n = base & (OUTN - 1);
        float4 s = *(const float4*)(skip_b + n);
        float4 p0 = *(const float4*)(g_part + 0ul * (BB * OUTN) + base);
        float4 p1 = *(const float4*)(g_part + 1ul * (BB * OUTN) + base);
        float4 p2 = *(const float4*)(g_part + 2ul * (BB * OUTN) + base);
        float4 p3 = *(const float4*)(g_part + 3ul * (BB * OUTN) + base);
        s.x += (p0.x + p1.x) + (p2.x + p3.x);
        s.y += (p0.y + p1.y) + (p2.y + p3.y);
        s.z += (p0.z + p1.z) + (p2.z + p3.z);
        s.w += (p0.w + p1.w) + (p2.w + p3.w);
        *(float4*)(y + base) = s;
    }
}

// ---------------------------------------------------------------------------
extern "C" void kernel_launch(void* const* d_in, const int* in_sizes, int n_in,
                              void* d_out, int out_size) {
    const float* x      = (const float*)d_in[0];  // (B, D)
    const float* values = (const float*)d_in[1];  // (OUT, D, K)
    const float* skip_w = (const float*)d_in[2];  // (OUT, D)
    const float* skip_b = (const float*)d_in[3];  // (OUT,)
    float* y = (float*)d_out;                     // (B, OUT)

    cudaFuncSetAttribute(k_gemm, cudaFuncAttributeMaxDynamicSharedMemorySize,
                         SMEM_BYTES);

    float* part;
    cudaGetSymbolAddress((void**)&part, g_part);

    k_build<<<VBLKS + BB, 256>>>(values, skip_w, x);
    k_gemm<<<KSPLIT * MTILES * NTILES, 256, SMEM_BYTES>>>(part);
    k_reduce<<<RHALF / 256, 256>>>(skip_b, y);
}

// round 12
// speedup vs baseline: 3.6246x; 1.0082x over previous
#include <cuda_runtime.h>
#include <cuda_fp16.h>
#include <cstdint>

// Problem constants
#define BB   2048
#define DD   256
#define OUTN 256
#define KK   16
#define DKN  (DD * KK)   // 4096 = GEMM K

// GEMM tiling
#define MT      128                // CTA M tile
#define NT      64                 // CTA N tile
#define KSPLIT  4
#define NKCH_S  16                 // chunks per K-split (64 total / 4)
#define MTILES  (BB / MT)          // 16
#define NTILES  (OUTN / NT)        // 4
#define STAGES  3
#define ASTG    16384              // 128 rows x 128B
#define BSTG    8192               // 64 rows x 128B
#define STG_BYTES (ASTG + BSTG)    // 24KB
#define SMEM_BYTES (STAGES * STG_BYTES)   // 72KB

// Scratch (device globals; no allocation allowed)
__device__ __half g_Phi[BB * DKN];            // 16 MB
__device__ __half g_V[OUTN * DKN];            //  2 MB
__device__ float  g_part[KSPLIT * BB * OUTN]; //  8 MB fp32 partials

__constant__ float c_grid[16] = {
    -1.0f,         -0.86666667f, -0.73333333f, -0.6f,
    -0.46666667f,  -0.33333334f, -0.2f,        -0.06666667f,
     0.06666667f,   0.2f,         0.33333333f,  0.46666667f,
     0.6f,          0.73333333f,  0.86666667f,  1.0f
};

// ---------------------------------------------------------------------------
// Bucketize (validated semantics R1-R11)
// ---------------------------------------------------------------------------
__device__ __forceinline__ void bucketize(float xv, int& l, float& w) {
    float xc = fminf(fmaxf(xv, -1.0f), 1.0f);
    float t = (xc + 1.0f) * 7.5f;
    int j = (int)t;
    if (j > 14) j = 14;
    if (j > 0 && xc <= c_grid[j]) {
        --j;
    } else if (j < 14 && xc > c_grid[j + 1]) {
        ++j;
    }
    float ww = (xc - c_grid[j]) / (c_grid[j + 1] - c_grid[j]);
    w = fminf(fmaxf(ww, 0.0f), 1.0f);
    l = j;
}

// Branch-free fp16 Phi row (8 half2 words). Validated in R9 (identical
// rounding/rel_err to the select-chain builder).
__device__ __forceinline__ void phi_pair(float xv, uint32_t* h /*[8]*/) {
    int l; float w;
    bucketize(xv, l, w);
    float f0 = 1.0f - w;
    uint32_t wv;   // {lo = f0, hi = w}
    asm("cvt.rn.f16x2.f32 %0, %1, %2;" : "=r"(wv) : "f"(w), "f"(f0));
    int  odd = l & 1;
    uint32_t A = odd ? (wv << 16) : wv;    // odd: pack(0, f0)
    uint32_t B = odd ? (wv >> 16) : 0u;    // odd: pack(w, 0)
    int pA = l >> 1;
    int pB = odd ? (pA + 1) : 8;           // 8 = never matches
#pragma unroll
    for (int i = 0; i < 8; ++i)
        h[i] = (i == pA) ? A : ((i == pB) ? B : 0u);
}

// ---------------------------------------------------------------------------
// Kernel 1: merged build.
//  Blocks [0, VBLKS)      : V' (8 halfs/thread, validated R9-R11)
//  Blocks [VBLKS, +PBLKS) : Phi (2 d's/thread, branch-free encoding)
// ---------------------------------------------------------------------------
#define VBLKS 512
#define PBLKS 1024
__global__ void k_build(const float* __restrict__ vals,
                        const float* __restrict__ sw,
                        const float* __restrict__ x) {
    int bid = blockIdx.x;
    int tid = threadIdx.x;
    if (bid < VBLKS) {
        int base = (bid * 256 + tid) * 8;
        int o  = base >> 12;
        int dk = base & 4095;
        float swv = sw[o * DD + (dk >> 4)];
        float4 v0 = *(const float4*)(vals + base);
        float4 v1 = *(const float4*)(vals + base + 4);
        const float* gr = c_grid + (dk & 15);

        __half hv[8];
        hv[0] = __float2half_rn(v0.x + gr[0] * swv);
        hv[1] = __float2half_rn(v0.y + gr[1] * swv);
        hv[2] = __float2half_rn(v0.z + gr[2] * swv);
        hv[3] = __float2half_rn(v0.w + gr[3] * swv);
        hv[4] = __float2half_rn(v1.x + gr[4] * swv);
        hv[5] = __float2half_rn(v1.y + gr[5] * swv);
        hv[6] = __float2half_rn(v1.z + gr[6] * swv);
        hv[7] = __float2half_rn(v1.w + gr[7] * swv);
        *(uint4*)(g_V + base) = *(const uint4*)hv;
    } else {
        int g  = (bid - VBLKS) * 256 + tid;   // 0 .. 262143
        int b  = g >> 7;
        int dp = (g & 127) * 2;
        float2 xv = *(const float2*)(x + b * DD + dp);
        __half* dst = g_Phi + b * DKN + dp * 16;

        uint32_t h[8];
        phi_pair(xv.x, h);
        *(uint4*)(dst)      = *(const uint4*)&h[0];
        *(uint4*)(dst + 8)  = *(const uint4*)&h[4];
        phi_pair(xv.y, h);
        *(uint4*)(dst + 16) = *(const uint4*)&h[0];
        *(uint4*)(dst + 24) = *(const uint4*)&h[4];
    }
}

// ---------------------------------------------------------------------------
// Kernel 2: HMMA GEMM, K-split=4. 256 CTAs x 256 threads (8 warps, 4x2 of
// 32x32 warp tiles). Unchanged from validated R11.
// ---------------------------------------------------------------------------
#define LDMX4(r0, r1, r2, r3, addr)                                       \
    asm volatile("ldmatrix.sync.aligned.m8n8.x4.shared.b16 "              \
                 "{%0,%1,%2,%3}, [%4];"                                   \
                 : "=r"(r0), "=r"(r1), "=r"(r2), "=r"(r3) : "r"(addr))

#define MMA16816(c, a0, a1, a2, a3, b0, b1)                               \
    asm volatile("mma.sync.aligned.m16n8k16.row.col.f32.f16.f16.f32 "     \
                 "{%0,%1,%2,%3}, {%4,%5,%6,%7}, {%8,%9}, {%0,%1,%2,%3};"  \
                 : "+f"(c[0]), "+f"(c[1]), "+f"(c[2]), "+f"(c[3])         \
                 : "r"(a0), "r"(a1), "r"(a2), "r"(a3), "r"(b0), "r"(b1))

__device__ __forceinline__ void load_stage(uint32_t sb, const char* gA,
                                           const char* gB, int kt, int slot,
                                           int tid) {
    uint32_t dstA = sb + slot * STG_BYTES;
    uint32_t dstB = dstA + ASTG;
    const char* srcA = gA + kt * 128;
    const char* srcB = gB + kt * 128;
#pragma unroll
    for (int i = 0; i < 4; ++i) {
        int idx = i * 256 + tid;
        int row = idx >> 3;
        int cb  = idx & 7;
        uint32_t swz = row * 128 + ((cb ^ (row & 7)) << 4);
        asm volatile("cp.async.cg.shared.global [%0], [%1], 16;"
                     :: "r"(dstA + swz), "l"(srcA + row * 8192 + cb * 16)
                     : "memory");
    }
#pragma unroll
    for (int i = 0; i < 2; ++i) {
        int idx = i * 256 + tid;
        int row = idx >> 3;
        int cb  = idx & 7;
        uint32_t swz = row * 128 + ((cb ^ (row & 7)) << 4);
        asm volatile("cp.async.cg.shared.global [%0], [%1], 16;"
                     :: "r"(dstB + swz), "l"(srcB + row * 8192 + cb * 16)
                     : "memory");
    }
}

__global__ __launch_bounds__(256) void k_gemm(float* __restrict__ part) {
    extern __shared__ char smem[];
    uint32_t sb;
    asm("{ .reg .u64 t; cvta.to.shared.u64 t, %1; cvt.u32.u64 %0, t; }"
        : "=r"(sb) : "l"(smem));

    const int tid  = threadIdx.x;
    const int wid  = tid >> 5;
    const int lane = tid & 31;
    const int wm   = (wid & 3) * 32;
    const int wn   = (wid >> 2) * 32;
    const int ks   = blockIdx.x >> 6;
    const int mt   = (blockIdx.x >> 2) & 15;
    const int nt   = blockIdx.x & 3;
    const char* gA = (const char*)g_Phi + (size_t)mt * MT * 8192 + ks * NKCH_S * 128;
    const char* gB = (const char*)g_V   + (size_t)nt * NT * 8192 + ks * NKCH_S * 128;

    const int lrow = lane & 15;
    const int lcb  = lane >> 4;

    load_stage(sb, gA, gB, 0, 0, tid);
    asm volatile("cp.async.commit_group;" ::: "memory");
    load_stage(sb, gA, gB, 1, 1, tid);
    asm volatile("cp.async.commit_group;" ::: "memory");

    float acc[2][4][4];
#pragma unroll
    for (int mi = 0; mi < 2; ++mi)
#pragma unroll
        for (int ni = 0; ni < 4; ++ni)
#pragma unroll
            for (int j = 0; j < 4; ++j) acc[mi][ni][j] = 0.f;

    const int arow0 = wm + lrow, arow1 = wm + 16 + lrow;
    const int brow0 = wn + lrow, brow1 = wn + 16 + lrow;

#pragma unroll 1
    for (int kt = 0; kt < NKCH_S; ++kt) {
        asm volatile("cp.async.wait_group 1;" ::: "memory");
        __syncthreads();

        if (kt + 2 < NKCH_S)
            load_stage(sb, gA, gB, kt + 2, (kt + 2) % STAGES, tid);
        asm volatile("cp.async.commit_group;" ::: "memory");

        uint32_t sA = sb + (kt % STAGES) * STG_BYTES;
        uint32_t sB = sA + ASTG;

#pragma unroll
        for (int k16 = 0; k16 < 4; ++k16) {
            int cu = k16 * 2 + lcb;
            uint32_t a0, a1, a2, a3, a4, a5, a6, a7;
            uint32_t b0, b1, b2, b3, b4, b5, b6, b7;
            LDMX4(a0, a1, a2, a3, sA + arow0 * 128 + ((cu ^ (arow0 & 7)) << 4));
            LDMX4(a4, a5, a6, a7, sA + arow1 * 128 + ((cu ^ (arow1 & 7)) << 4));
            LDMX4(b0, b1, b2, b3, sB + brow0 * 128 + ((cu ^ (brow0 & 7)) << 4));
            LDMX4(b4, b5, b6, b7, sB + brow1 * 128 + ((cu ^ (brow1 & 7)) << 4));

            MMA16816(acc[0][0], a0, a1, a2, a3, b0, b2);
            MMA16816(acc[0][1], a0, a1, a2, a3, b1, b3);
            MMA16816(acc[0][2], a0, a1, a2, a3, b4, b6);
            MMA16816(acc[0][3], a0, a1, a2, a3, b5, b7);
            MMA16816(acc[1][0], a4, a5, a6, a7, b0, b2);
            MMA16816(acc[1][1], a4, a5, a6, a7, b1, b3);
            MMA16816(acc[1][2], a4, a5, a6, a7, b4, b6);
            MMA16816(acc[1][3], a4, a5, a6, a7, b5, b7);
        }
    }

    float* pout = part + (size_t)ks * (BB * OUTN);
    const int m0 = mt * MT + wm + (lane >> 2);
    const int nb = nt * NT + wn + (lane & 3) * 2;
#pragma unroll
    for (int mi = 0; mi < 2; ++mi) {
#pragma unroll
        for (int ni = 0; ni < 4; ++ni) {
            int n = nb + ni * 8;
            int m = m0 + mi * 16;
            *(float2*)(pout + m * OUTN + n) =
                make_float2(acc[mi][ni][0], acc[mi][ni][1]);
            *(float2*)(pout + (m + 8) * OUTN + n) =
                make_float2(acc[mi][ni][2], acc[mi][ni][3]);
        }
    }
}

// ---------------------------------------------------------------------------
// Kernel 3: reduce partials + bias (validated R11)
// ---------------------------------------------------------------------------
#define RHALF (BB * OUTN / 8)   // 65536 float4s per half
__global__ void k_reduce(const float* __restrict__ skip_b,
                         float* __restrict__ y) {
    int gid = blockIdx.x * 256 + threadIdx.x;
#pragma unroll
    for (int j = 0; j < 2; ++j) {
        int base = (gid + j * RHALF) * 4;
        int n = base & (OUTN - 1);
        float4 s = *(const float4*)(skip_b + n);
        float4 p0 = *(const float4*)(g_part + 0ul * (BB * OUTN) + base);
        float4 p1 = *(const float4*)(g_part + 1ul * (BB * OUTN) + base);
        float4 p2 = *(const float4*)(g_part + 2ul * (BB * OUTN) + base);
        float4 p3 = *(const float4*)(g_part + 3ul * (BB * OUTN) + base);
        s.x += (p0.x + p1.x) + (p2.x + p3.x);
        s.y += (p0.y + p1.y) + (p2.y + p3.y);
        s.z += (p0.z + p1.z) + (p2.z + p3.z);
        s.w += (p0.w + p1.w) + (p2.w + p3.w);
        *(float4*)(y + base) = s;
    }
}

// ---------------------------------------------------------------------------
extern "C" void kernel_launch(void* const* d_in, const int* in_sizes, int n_in,
                              void* d_out, int out_size) {
    const float* x      = (const float*)d_in[0];  // (B, D)
    const float* values = (const float*)d_in[1];  // (OUT, D, K)
    const float* skip_w = (const float*)d_in[2];  // (OUT, D)
    const float* skip_b = (const float*)d_in[3];  // (OUT,)
    float* y = (float*)d_out;                     // (B, OUT)

    cudaFuncSetAttribute(k_gemm, cudaFuncAttributeMaxDynamicSharedMemorySize,
                         SMEM_BYTES);

    float* part;
    cudaGetSymbolAddress((void**)&part, g_part);

    k_build<<<VBLKS + PBLKS, 256>>>(values, skip_w, x);
    k_gemm<<<KSPLIT * MTILES * NTILES, 256, SMEM_BYTES>>>(part);
    k_reduce<<<RHALF / 256, 256>>>(skip_b, y);
}